// round 5
// baseline (speedup 1.0000x reference)
#include <cuda_runtime.h>
#include <cstdint>

#define BLOCK 128
#define MTILE 64
#define MM 16
#define NMAX 8192

// prologue-packed operands
__device__ float4   g_y4[NMAX];                // (-2yx, -2yy, -2yz, |y|^2)
__device__ uint32_t g_bh[(NMAX / 2) * MM];     // bf16x2 hi of 0.5*ln2*coeff pairs
__device__ uint32_t g_bl[(NMAX / 2) * MM];     // bf16x2 lo residual

#define HALF_LN2 0.34657359027997264f

__device__ __forceinline__ uint32_t pack_bf16x2(float lo, float hi) {
    uint32_t d;
    asm("cvt.rn.bf16x2.f32 %0, %1, %2;" : "=r"(d) : "f"(hi), "f"(lo));
    return d;
}

__device__ __forceinline__ void split2(float f0, float f1, uint32_t& hi, uint32_t& lo) {
    hi = pack_bf16x2(f0, f1);
    float h0 = __uint_as_float(hi << 16);
    float h1 = __uint_as_float(hi & 0xffff0000u);
    lo = pack_bf16x2(f0 - h0, f1 - h1);
}

__device__ __forceinline__ void mma_bf16(float* c, const uint32_t* a, uint32_t b0, uint32_t b1) {
    asm volatile(
        "mma.sync.aligned.m16n8k16.row.col.f32.bf16.bf16.f32 "
        "{%0,%1,%2,%3}, {%4,%5,%6,%7}, {%8,%9}, {%0,%1,%2,%3};"
        : "+f"(c[0]), "+f"(c[1]), "+f"(c[2]), "+f"(c[3])
        : "r"(a[0]), "r"(a[1]), "r"(a[2]), "r"(a[3]), "r"(b0), "r"(b1));
}

// A value = s * lg2(s); the 0.5*ln2 factor lives in B. s = |x-y|^2, sqrt-free.
__device__ __forceinline__ float phi_f(float4 xr, float4 v) {
    float t = fmaf(xr.x, v.x, fmaf(xr.y, v.y, fmaf(xr.z, v.z, v.w)));
    float s = xr.w + t;
    s = fmaxf(s, 1e-14f);
    return s * __log2f(s);
}

__device__ __forceinline__ uint32_t smem_u32(const void* p) {
    uint32_t a;
    asm("{ .reg .u64 t; cvta.to.shared.u64 t, %1; cvt.u32.u64 %0, t; }" : "=r"(a) : "l"(p));
    return a;
}

#define CP16(dst_u32, src_ptr) \
    asm volatile("cp.async.cg.shared.global [%0], [%1], 16;" :: "r"(dst_u32), "l"(src_ptr))

// ---------------- prologue ----------------
__global__ void prep_kernel(const float* __restrict__ y,
                            const float* __restrict__ coeffs,
                            int n, int npad) {
    int i = blockIdx.x * blockDim.x + threadIdx.x;
    if (i < npad) {
        float4 v = make_float4(0.f, 0.f, 0.f, 1.f);
        if (i < n) {
            float a = y[3 * i], b = y[3 * i + 1], c = y[3 * i + 2];
            v = make_float4(-2.f * a, -2.f * b, -2.f * c, fmaf(a, a, fmaf(b, b, c * c)));
        }
        g_y4[i] = v;
    }
    int npe = (npad >> 1) * MM;
    if (i < npe) {
        int p = i >> 4, c = i & 15;
        int j0 = 2 * p, j1 = 2 * p + 1;
        float f0 = (j0 < n) ? HALF_LN2 * coeffs[(size_t)j0 * MM + c] : 0.f;
        float f1 = (j1 < n) ? HALF_LN2 * coeffs[(size_t)j1 * MM + c] : 0.f;
        uint32_t hi, lo;
        split2(f0, f1, hi, lo);
        g_bh[i] = hi;
        g_bl[i] = lo;
    }
}

// ---------------- main kernel ----------------
__global__ __launch_bounds__(BLOCK) void rbf_tps_mma_kernel(
    const float* __restrict__ x,
    const float* __restrict__ shift,
    const float* __restrict__ scale,
    const float* __restrict__ coeffs,
    const int*   __restrict__ powers,
    float* __restrict__ out,
    int nx, int n, int npad, int r)
{
    __shared__ float4   sy[2][64];
    __shared__ uint32_t sbh[2][512];
    __shared__ uint32_t sbl[2][512];
    __shared__ float    sred[2][32][MM];

    const int tid  = threadIdx.x;
    const int lane = tid & 31;
    const int w    = tid >> 5;
    const int t4   = lane & 3;
    const int g    = lane >> 2;
    const int rowhalf = w & 1;
    const int jhalf   = w >> 1;

    const int rowbase = blockIdx.x * MTILE + rowhalf * 32;

    float4 xr[4];
#pragma unroll
    for (int i = 0; i < 4; ++i) {
        int row = rowbase + g + 8 * i;
        float4 v = make_float4(0.f, 0.f, 0.f, 0.f);
        if (row < nx) {
            v.x = x[3 * row + 0];
            v.y = x[3 * row + 1];
            v.z = x[3 * row + 2];
            v.w = fmaf(v.x, v.x, fmaf(v.y, v.y, v.z * v.z));
        }
        xr[i] = v;
    }

    float acc[2][2][4];
#pragma unroll
    for (int a = 0; a < 2; ++a)
#pragma unroll
        for (int b = 0; b < 2; ++b)
#pragma unroll
            for (int c = 0; c < 4; ++c) acc[a][b][c] = 0.f;

    const int nchunks = npad >> 6;

    // prefetch chunk 0
    {
        int j0 = 0;
        if (tid < 64) CP16(smem_u32(&sy[0][tid]), &g_y4[j0 + tid]);
        CP16(smem_u32(&sbh[0][tid * 4]), &g_bh[(j0 >> 1) * MM + tid * 4]);
        CP16(smem_u32(&sbl[0][tid * 4]), &g_bl[(j0 >> 1) * MM + tid * 4]);
        asm volatile("cp.async.commit_group;" ::: "memory");
    }

    for (int t = 0; t < nchunks; ++t) {
        const int buf = t & 1;

        // prefetch chunk t+1 into the other buffer
        if (t + 1 < nchunks) {
            int j0 = (t + 1) * 64, nb = buf ^ 1;
            if (tid < 64) CP16(smem_u32(&sy[nb][tid]), &g_y4[j0 + tid]);
            CP16(smem_u32(&sbh[nb][tid * 4]), &g_bh[(j0 >> 1) * MM + tid * 4]);
            CP16(smem_u32(&sbl[nb][tid * 4]), &g_bl[(j0 >> 1) * MM + tid * 4]);
        }
        asm volatile("cp.async.commit_group;" ::: "memory");
        asm volatile("cp.async.wait_group 1;" ::: "memory");
        __syncthreads();

#pragma unroll
        for (int kk = 0; kk < 2; ++kk) {
            const int jbl = (jhalf * 2 + kk) * 16;   // local j base of this k-step
            const int j0l = jbl + 2 * t4;

            float4 v0 = sy[buf][j0l];
            float4 v1 = sy[buf][j0l + 1];
            float4 v2 = sy[buf][j0l + 8];
            float4 v3 = sy[buf][j0l + 9];

            const int p0 = (jbl >> 1) + t4;
            uint32_t bh[2][2], bl[2][2];
#pragma unroll
            for (int nt = 0; nt < 2; ++nt) {
                int c = g + 8 * nt;
                bh[nt][0] = sbh[buf][p0 * MM + c];
                bh[nt][1] = sbh[buf][(p0 + 4) * MM + c];
                bl[nt][0] = sbl[buf][p0 * MM + c];
                bl[nt][1] = sbl[buf][(p0 + 4) * MM + c];
            }

#pragma unroll
            for (int rt = 0; rt < 2; ++rt) {
                float4 xa = xr[2 * rt], xb = xr[2 * rt + 1];
                float p00 = phi_f(xa, v0), p01 = phi_f(xa, v1);
                float p02 = phi_f(xa, v2), p03 = phi_f(xa, v3);
                float p10 = phi_f(xb, v0), p11 = phi_f(xb, v1);
                float p12 = phi_f(xb, v2), p13 = phi_f(xb, v3);

                uint32_t ah[4], al[4];
                split2(p00, p01, ah[0], al[0]);
                split2(p10, p11, ah[1], al[1]);
                split2(p02, p03, ah[2], al[2]);
                split2(p12, p13, ah[3], al[3]);

#pragma unroll
                for (int nt = 0; nt < 2; ++nt) {
                    mma_bf16(acc[rt][nt], ah, bh[nt][0], bh[nt][1]);
                    mma_bf16(acc[rt][nt], al, bh[nt][0], bh[nt][1]);
                    mma_bf16(acc[rt][nt], ah, bl[nt][0], bl[nt][1]);
                }
            }
        }
        __syncthreads();   // done with buf before it is overwritten
    }

    // ---- combine j-halves ----
    if (w >= 2) {
#pragma unroll
        for (int rt = 0; rt < 2; ++rt)
#pragma unroll
            for (int nt = 0; nt < 2; ++nt)
#pragma unroll
                for (int q = 0; q < 4; ++q)
                    sred[w - 2][lane][rt * 8 + nt * 4 + q] = acc[rt][nt][q];
    }
    __syncthreads();
    if (w >= 2) return;

#pragma unroll
    for (int rt = 0; rt < 2; ++rt)
#pragma unroll
        for (int nt = 0; nt < 2; ++nt)
#pragma unroll
            for (int q = 0; q < 4; ++q)
                acc[rt][nt][q] += sred[w][lane][rt * 8 + nt * 4 + q];

    // ---- epilogue: polynomial part (unscaled coeffs) + store ----
    const float sh0 = __ldg(&shift[0]), sh1 = __ldg(&shift[1]), sh2 = __ldg(&shift[2]);
    const float sl0 = __ldg(&scale[0]), sl1 = __ldg(&scale[1]), sl2 = __ldg(&scale[2]);

#pragma unroll
    for (int i = 0; i < 4; ++i) {
        int grow = rowbase + g + 8 * i;
        if (grow >= nx) continue;
        float4 xc = xr[i];
        float xh0 = (xc.x - sh0) / sl0;
        float xh1 = (xc.y - sh1) / sl1;
        float xh2 = (xc.z - sh2) / sl2;
        const int rt = i >> 1, up = i & 1;

#pragma unroll
        for (int nt = 0; nt < 2; ++nt) {
            const int col = 2 * t4 + 8 * nt;
            float o0 = acc[rt][nt][up * 2 + 0];
            float o1 = acc[rt][nt][up * 2 + 1];
            for (int k = 0; k < r; ++k) {
                float p = 1.f;
                int e0 = __ldg(&powers[k * 3 + 0]);
                int e1 = __ldg(&powers[k * 3 + 1]);
                int e2 = __ldg(&powers[k * 3 + 2]);
                for (int q = 0; q < e0; ++q) p *= xh0;
                for (int q = 0; q < e1; ++q) p *= xh1;
                for (int q = 0; q < e2; ++q) p *= xh2;
                float cc0 = __ldg(&coeffs[(size_t)(n + k) * MM + col]);
                float cc1 = __ldg(&coeffs[(size_t)(n + k) * MM + col + 1]);
                o0 = fmaf(p, cc0, o0);
                o1 = fmaf(p, cc1, o1);
            }
            *reinterpret_cast<float2*>(&out[(size_t)grow * MM + col]) = make_float2(o0, o1);
        }
    }
}

extern "C" void kernel_launch(void* const* d_in, const int* in_sizes, int n_in,
                              void* d_out, int out_size) {
    const float* x      = (const float*)d_in[0];
    const float* y      = (const float*)d_in[1];
    const float* shift  = (const float*)d_in[2];
    const float* scale  = (const float*)d_in[3];
    const float* coeffs = (const float*)d_in[4];
    const int*   powers = (const int*)d_in[5];

    int nx = in_sizes[0] / 3;
    int n  = in_sizes[1] / 3;
    int r  = in_sizes[5] / 3;

    int npad = (n + 63) & ~63;
    if (npad > NMAX) npad = NMAX;

    int prep_work = (npad >> 1) * MM;
    if (npad > prep_work) prep_work = npad;
    prep_kernel<<<(prep_work + 255) / 256, 256>>>(y, coeffs, n, npad);

    int grid = (nx + MTILE - 1) / MTILE;
    rbf_tps_mma_kernel<<<grid, BLOCK>>>(x, shift, scale, coeffs, powers,
                                        (float*)d_out, nx, n, npad, r);
}

// round 6
// speedup vs baseline: 1.0399x; 1.0399x over previous
#include <cuda_runtime.h>
#include <cstdint>

#define BLOCK 128
#define MTILE 32
#define MM 16
#define NMAX 8192
#define CHUNK 128
#define HALF_LN2 0.34657359027997264f

// prologue-packed operands
__device__ float4 g_y4[NMAX];               // (-2yx, -2yy, -2yz, |y|^2); pad = (0,0,0,1)
__device__ uint2  g_b[(NMAX / 2) * MM];     // {hi,lo} bf16x2 of (0.5*ln2*coeff) pairs

__device__ __forceinline__ uint32_t pack_bf16x2(float lo, float hi) {
    uint32_t d;
    asm("cvt.rn.bf16x2.f32 %0, %1, %2;" : "=r"(d) : "f"(hi), "f"(lo));
    return d;
}

__device__ __forceinline__ void split2(float f0, float f1, uint32_t& hi, uint32_t& lo) {
    hi = pack_bf16x2(f0, f1);
    float h0 = __uint_as_float(hi << 16);
    float h1 = __uint_as_float(hi & 0xffff0000u);
    lo = pack_bf16x2(f0 - h0, f1 - h1);
}

__device__ __forceinline__ void mma_bf16(float* c, const uint32_t* a, uint32_t b0, uint32_t b1) {
    asm volatile(
        "mma.sync.aligned.m16n8k16.row.col.f32.bf16.bf16.f32 "
        "{%0,%1,%2,%3}, {%4,%5,%6,%7}, {%8,%9}, {%0,%1,%2,%3};"
        : "+f"(c[0]), "+f"(c[1]), "+f"(c[2]), "+f"(c[3])
        : "r"(a[0]), "r"(a[1]), "r"(a[2]), "r"(a[3]), "r"(b0), "r"(b1));
}

// A value = s * lg2(s); 0.5*ln2 folded into B. s = |x-y|^2 (sqrt-free).
__device__ __forceinline__ float phi_f(float4 xr, float4 v) {
    float t = fmaf(xr.x, v.x, fmaf(xr.y, v.y, fmaf(xr.z, v.z, v.w)));
    float s = xr.w + t;
    s = fmaxf(s, 1e-14f);
    return s * __log2f(s);
}

__device__ __forceinline__ uint32_t smem_u32(const void* p) {
    uint32_t a;
    asm("{ .reg .u64 t; cvta.to.shared.u64 t, %1; cvt.u32.u64 %0, t; }" : "=r"(a) : "l"(p));
    return a;
}

#define CP16(dst_u32, src_ptr) \
    asm volatile("cp.async.cg.shared.global [%0], [%1], 16;" :: "r"(dst_u32), "l"(src_ptr))

// ---------------- prologue ----------------
__global__ void prep_kernel(const float* __restrict__ y,
                            const float* __restrict__ coeffs,
                            int n, int npad) {
    int i = blockIdx.x * blockDim.x + threadIdx.x;
    if (i < npad) {
        float4 v = make_float4(0.f, 0.f, 0.f, 1.f);
        if (i < n) {
            float a = y[3 * i], b = y[3 * i + 1], c = y[3 * i + 2];
            v = make_float4(-2.f * a, -2.f * b, -2.f * c, fmaf(a, a, fmaf(b, b, c * c)));
        }
        g_y4[i] = v;
    }
    int npe = (npad >> 1) * MM;
    if (i < npe) {
        int p = i >> 4, c = i & 15;
        int j0 = 2 * p, j1 = 2 * p + 1;
        float f0 = (j0 < n) ? HALF_LN2 * coeffs[(size_t)j0 * MM + c] : 0.f;
        float f1 = (j1 < n) ? HALF_LN2 * coeffs[(size_t)j1 * MM + c] : 0.f;
        uint32_t hi, lo;
        split2(f0, f1, hi, lo);
        g_b[i] = make_uint2(hi, lo);
    }
}

// ---------------- main kernel ----------------
__global__ __launch_bounds__(BLOCK) void rbf_tps_mma_kernel(
    const float* __restrict__ x,
    const float* __restrict__ shift,
    const float* __restrict__ scale,
    const float* __restrict__ coeffs,
    const int*   __restrict__ powers,
    float* __restrict__ out,
    int nx, int n, int npad, int r)
{
    __shared__ float4 sy[2][CHUNK];                 // 4 KB
    __shared__ uint2  sb[2][(CHUNK / 2) * MM];      // 16 KB, XOR-swizzled layout
    __shared__ float  sred[3][32][MM];              // 6 KB

    const int tid  = threadIdx.x;
    const int lane = tid & 31;
    const int w    = tid >> 5;
    const int t4   = lane & 3;
    const int g    = lane >> 2;

    const int tilebase = blockIdx.x * MTILE;

    // rows g, g+8, g+16, g+24 of this 32-row tile
    float4 xr[4];
#pragma unroll
    for (int i = 0; i < 4; ++i) {
        int row = tilebase + g + 8 * i;
        float4 v = make_float4(0.f, 0.f, 0.f, 0.f);
        if (row < nx) {
            v.x = x[3 * row + 0];
            v.y = x[3 * row + 1];
            v.z = x[3 * row + 2];
            v.w = fmaf(v.x, v.x, fmaf(v.y, v.y, v.z * v.z));
        }
        xr[i] = v;
    }

    float acc[2][2][4];
#pragma unroll
    for (int a = 0; a < 2; ++a)
#pragma unroll
        for (int b = 0; b < 2; ++b)
#pragma unroll
            for (int c = 0; c < 4; ++c) acc[a][b][c] = 0.f;

    const int nchunks = npad / CHUNK;   // even (npad % 256 == 0)

    // lane-constant swizzled B column indices (swizzle = XOR 8*((p>>1)&1), p&2 == t4&2)
    const int csw0 = g ^ ((t4 & 2) << 2);        // nt=0
    const int csw1 = (g + 8) ^ ((t4 & 2) << 2);  // nt=1

    // ---- prefetch helpers (inlined below; all offsets static per buf literal) ----
#define PREFETCH(c0, buf)                                                          \
    do {                                                                           \
        CP16(smem_u32(&sy[buf][tid]), &g_y4[(c0) * CHUNK + tid]);                  \
        _Pragma("unroll")                                                          \
        for (int q = 0; q < 4; ++q) {                                              \
            int flat = tid * 8 + q * 2;                                            \
            int p = flat >> 4, c = flat & 15;                                      \
            int dsti = p * 16 + (c ^ (((p >> 1) & 1) << 3));                       \
            CP16(smem_u32(&sb[buf][dsti]), &g_b[(size_t)(c0) * (CHUNK / 2) * MM + flat]); \
        }                                                                          \
        asm volatile("cp.async.commit_group;" ::: "memory");                       \
    } while (0)

#define DO_CHUNK(buf)                                                              \
    do {                                                                           \
        _Pragma("unroll")                                                          \
        for (int kk = 0; kk < 2; ++kk) {                                           \
            const int jbl = w * 32 + kk * 16;                                      \
            const int j0l = jbl + 2 * t4;                                          \
            float4 v0 = sy[buf][j0l];                                              \
            float4 v1 = sy[buf][j0l + 1];                                          \
            float4 v2 = sy[buf][j0l + 8];                                          \
            float4 v3 = sy[buf][j0l + 9];                                          \
            const int p0 = (jbl >> 1) + t4;                                        \
            uint2 b00 = sb[buf][p0 * MM + csw0];                                   \
            uint2 b01 = sb[buf][(p0 + 4) * MM + csw0];                             \
            uint2 b10 = sb[buf][p0 * MM + csw1];                                   \
            uint2 b11 = sb[buf][(p0 + 4) * MM + csw1];                             \
            _Pragma("unroll")                                                      \
            for (int rt = 0; rt < 2; ++rt) {                                       \
                float4 xa = xr[2 * rt], xb = xr[2 * rt + 1];                       \
                float p00 = phi_f(xa, v0), p01 = phi_f(xa, v1);                    \
                float p02 = phi_f(xa, v2), p03 = phi_f(xa, v3);                    \
                float p10 = phi_f(xb, v0), p11 = phi_f(xb, v1);                    \
                float p12 = phi_f(xb, v2), p13 = phi_f(xb, v3);                    \
                uint32_t ah[4], al[4];                                             \
                split2(p00, p01, ah[0], al[0]);                                    \
                split2(p10, p11, ah[1], al[1]);                                    \
                split2(p02, p03, ah[2], al[2]);                                    \
                split2(p12, p13, ah[3], al[3]);                                    \
                mma_bf16(acc[rt][0], ah, b00.x, b01.x);                            \
                mma_bf16(acc[rt][0], al, b00.x, b01.x);                            \
                mma_bf16(acc[rt][0], ah, b00.y, b01.y);                            \
                mma_bf16(acc[rt][1], ah, b10.x, b11.x);                            \
                mma_bf16(acc[rt][1], al, b10.x, b11.x);                            \
                mma_bf16(acc[rt][1], ah, b10.y, b11.y);                            \
            }                                                                      \
        }                                                                          \
    } while (0)

    PREFETCH(0, 0);
    PREFETCH(1, 1);

    for (int t = 0; t < nchunks; t += 2) {
        // ---- buffer 0: chunk t ----
        asm volatile("cp.async.wait_group 1;" ::: "memory");
        __syncthreads();
        DO_CHUNK(0);
        __syncthreads();
        if (t + 2 < nchunks) PREFETCH(t + 2, 0);
        else asm volatile("cp.async.commit_group;" ::: "memory");

        // ---- buffer 1: chunk t+1 ----
        asm volatile("cp.async.wait_group 1;" ::: "memory");
        __syncthreads();
        DO_CHUNK(1);
        __syncthreads();
        if (t + 3 < nchunks) PREFETCH(t + 3, 1);
        else asm volatile("cp.async.commit_group;" ::: "memory");
    }
    asm volatile("cp.async.wait_group 0;" ::: "memory");

    // ---- 4-way j combine: warps 1-3 publish, warp 0 reduces ----
    if (w > 0) {
#pragma unroll
        for (int rt = 0; rt < 2; ++rt)
#pragma unroll
            for (int nt = 0; nt < 2; ++nt)
#pragma unroll
                for (int q = 0; q < 4; ++q)
                    sred[w - 1][lane][rt * 8 + nt * 4 + q] = acc[rt][nt][q];
    }
    __syncthreads();
    if (w > 0) return;

#pragma unroll
    for (int ww = 0; ww < 3; ++ww)
#pragma unroll
        for (int rt = 0; rt < 2; ++rt)
#pragma unroll
            for (int nt = 0; nt < 2; ++nt)
#pragma unroll
                for (int q = 0; q < 4; ++q)
                    acc[rt][nt][q] += sred[ww][lane][rt * 8 + nt * 4 + q];

    // ---- epilogue: polynomial part (unscaled coeffs) + store ----
    const float sh0 = __ldg(&shift[0]), sh1 = __ldg(&shift[1]), sh2 = __ldg(&shift[2]);
    const float sl0 = __ldg(&scale[0]), sl1 = __ldg(&scale[1]), sl2 = __ldg(&scale[2]);

#pragma unroll
    for (int i = 0; i < 4; ++i) {
        int grow = tilebase + g + 8 * i;
        if (grow >= nx) continue;
        float4 xc = xr[i];
        float xh0 = (xc.x - sh0) / sl0;
        float xh1 = (xc.y - sh1) / sl1;
        float xh2 = (xc.z - sh2) / sl2;
        const int rt = i >> 1, up = i & 1;

#pragma unroll
        for (int nt = 0; nt < 2; ++nt) {
            const int col = 2 * t4 + 8 * nt;
            float o0 = acc[rt][nt][up * 2 + 0];
            float o1 = acc[rt][nt][up * 2 + 1];
            for (int k = 0; k < r; ++k) {
                float p = 1.f;
                int e0 = __ldg(&powers[k * 3 + 0]);
                int e1 = __ldg(&powers[k * 3 + 1]);
                int e2 = __ldg(&powers[k * 3 + 2]);
                for (int q = 0; q < e0; ++q) p *= xh0;
                for (int q = 0; q < e1; ++q) p *= xh1;
                for (int q = 0; q < e2; ++q) p *= xh2;
                float cc0 = __ldg(&coeffs[(size_t)(n + k) * MM + col]);
                float cc1 = __ldg(&coeffs[(size_t)(n + k) * MM + col + 1]);
                o0 = fmaf(p, cc0, o0);
                o1 = fmaf(p, cc1, o1);
            }
            *reinterpret_cast<float2*>(&out[(size_t)grow * MM + col]) = make_float2(o0, o1);
        }
    }
}

extern "C" void kernel_launch(void* const* d_in, const int* in_sizes, int n_in,
                              void* d_out, int out_size) {
    const float* x      = (const float*)d_in[0];
    const float* y      = (const float*)d_in[1];
    const float* shift  = (const float*)d_in[2];
    const float* scale  = (const float*)d_in[3];
    const float* coeffs = (const float*)d_in[4];
    const int*   powers = (const int*)d_in[5];

    int nx = in_sizes[0] / 3;
    int n  = in_sizes[1] / 3;
    int r  = in_sizes[5] / 3;

    int npad = (n + 255) & ~255;     // even number of 128-chunks
    if (npad > NMAX) npad = NMAX;

    int prep_work = (npad >> 1) * MM;
    if (npad > prep_work) prep_work = npad;
    prep_kernel<<<(prep_work + 255) / 256, 256>>>(y, coeffs, n, npad);

    int grid = (nx + MTILE - 1) / MTILE;
    rbf_tps_mma_kernel<<<grid, BLOCK>>>(x, shift, scale, coeffs, powers,
                                        (float*)d_out, nx, n, npad, r);
}